// round 13
// baseline (speedup 1.0000x reference)
#include <cuda_runtime.h>
#include <cstdint>

// Problem constants
#define MAX_DIST 35.0f
#define BOX 71            // ceil(2*35/1 + 1)
#define FDIM 32
#define BATCH 8
#define NPTS 16384

#define NPOINTS (BATCH * NPTS)               // 131,072
#define NCELLS  (BOX * BOX * BOX)            // 357,911
#define SLICE0_F4 (NCELLS * (FDIM / 4))      // 2,863,288 float4 = slice 0
#define TOTAL_F4  (SLICE0_F4 * BATCH)        // 22,906,304

// Per-cell linked lists. Sentinel = 0; entries store pid+1.
// K0 re-initializes heads every call (also keeps the array L2-hot for K2).
__device__ int d_head[NCELLS];               // 1.4 MB
__device__ int d_next[NPOINTS];              // 0.5 MB

// ---------------------------------------------------------------------------
// K0: reset list heads (and warm them into L2 for K1's exchanges and K2's
// reads). Tiny; hidden under the PDL chain.
// ---------------------------------------------------------------------------
__global__ void __launch_bounds__(256)
init_heads_kernel() {
    int i = blockIdx.x * blockDim.x + threadIdx.x;
    if (i < NCELLS) d_head[i] = 0;
}

// ---------------------------------------------------------------------------
// K1 (PDL over K0): build per-cell lists. cell = round-half-to-even(c+35)
// per axis (faithful to jnp.round); out-of-box points excluded (they add
// exactly +0.0 in the reference). ALL B*N points map into batch slice 0
// (reference's tf.zeros batch column). Stores pid+1 (0 = end of list).
// ---------------------------------------------------------------------------
__global__ void __launch_bounds__(256)
build_lists_kernel(const float* __restrict__ coords) {
    int i = blockIdx.x * blockDim.x + threadIdx.x;    // 0 .. NPOINTS-1
    float c0 = __ldg(&coords[i * 3 + 0]);
    float c1 = __ldg(&coords[i * 3 + 1]);
    float c2 = __ldg(&coords[i * 3 + 2]);
    int g0 = __float2int_rn(c0 + MAX_DIST);
    int g1 = __float2int_rn(c1 + MAX_DIST);
    int g2 = __float2int_rn(c2 + MAX_DIST);

    cudaGridDependencySynchronize();   // K0's head init must be visible
    if ((unsigned)g0 < BOX && (unsigned)g1 < BOX && (unsigned)g2 < BOX) {
        int cell = (g0 * BOX + g1) * BOX + g2;
        d_next[i] = atomicExch(&d_head[cell], i + 1);
    }
}

// ---------------------------------------------------------------------------
// K2 (PDL over K1): gather + zero. One thread per (cell, quad).
//   1. 4 zero batches into slices 1..4 (pre-sync; overlaps K0+K1),
//   2. PDL sync, then ISSUE the head load immediately,
//   3. 3 zero batches into slices 5..7 (hide the head-load latency),
//   4. walk the cell's list accumulating feats[pid*8+q] (8 quad-threads of
//      a cell share one warp -> 128B-coalesced feature reads),
//   5. stream the accumulated float4 as the slice-0 value.
// Every output byte written exactly once; no atomics on the output.
// ---------------------------------------------------------------------------
__global__ void __launch_bounds__(256)
gather_zero_kernel(const float4* __restrict__ feats,
                   float* __restrict__ out) {
    const int tid = blockIdx.x * blockDim.x + threadIdx.x;
    if (tid >= SLICE0_F4) return;                  // 72 pad threads

    float4* out4 = (float4*)out;
    const float4 z = make_float4(0.f, 0.f, 0.f, 0.f);

    // Pre-sync zeros: slices 1..4 (64 MB grid-wide, covers K0+K1 runtime).
    #pragma unroll
    for (int k = 1; k <= 4; k++) {
        __stcs(&out4[(long long)k * SLICE0_F4 + tid], z);
    }

    cudaGridDependencySynchronize();               // wait for K1's lists

    const int cell = tid >> 3;
    const int q = tid & 7;

    int e = d_head[cell];                          // issue load NOW

    // Post-sync zeros: slices 5..7 — independent stores hide head latency.
    #pragma unroll
    for (int k = 5; k <= 7; k++) {
        __stcs(&out4[(long long)k * SLICE0_F4 + tid], z);
    }

    float4 acc = z;
    while (e != 0) {
        int pid = e - 1;
        float4 v = __ldg(&feats[(long long)pid * 8 + q]);
        acc.x += v.x; acc.y += v.y; acc.z += v.z; acc.w += v.w;
        e = d_next[pid];
    }
    __stcs(&out4[tid], acc);                       // slice 0, written once
}

extern "C" void kernel_launch(void* const* d_in, const int* in_sizes, int n_in,
                              void* d_out, int out_size) {
    const float* coords = (const float*)d_in[0];     // [8,16384,3] f32
    const float4* feats = (const float4*)d_in[1];    // [8,16384,32] f32 as float4
    float* out = (float*)d_out;                      // [8,71,71,71,32] f32

    cudaLaunchAttribute pdl[1];
    pdl[0].id = cudaLaunchAttributeProgrammaticStreamSerialization;
    pdl[0].val.programmaticStreamSerializationAllowed = 1;

    // K0: reset + warm heads.
    init_heads_kernel<<<(NCELLS + 255) / 256, 256>>>();

    // K1: build lists — PDL early launch over K0.
    {
        cudaLaunchConfig_t cfg = {};
        cfg.gridDim = dim3(NPOINTS / 256, 1, 1);     // 512 blocks
        cfg.blockDim = dim3(256, 1, 1);
        cfg.attrs = pdl; cfg.numAttrs = 1;
        cudaLaunchKernelEx(&cfg, build_lists_kernel, coords);
    }

    // K2: gather + zero — PDL early launch over K1.
    {
        cudaLaunchConfig_t cfg = {};
        cfg.gridDim = dim3((SLICE0_F4 + 255) / 256, 1, 1);  // 11185 blocks
        cfg.blockDim = dim3(256, 1, 1);
        cfg.attrs = pdl; cfg.numAttrs = 1;
        cudaLaunchKernelEx(&cfg, gather_zero_kernel, feats, out);
    }
}

// round 14
// speedup vs baseline: 1.0113x; 1.0113x over previous
#include <cuda_runtime.h>
#include <cstdint>

// Problem constants
#define MAX_DIST 35.0f
#define BOX 71            // ceil(2*35/1 + 1)
#define FDIM 32
#define BATCH 8
#define NPTS 16384

#define NPOINTS (BATCH * NPTS)               // 131,072
#define NCELLS  (BOX * BOX * BOX)            // 357,911
#define NCELLS_PAD 357912                    // NCELLS rounded to /4 for int4
#define SLICE0_F4 (NCELLS * (FDIM / 4))      // 2,863,288 float4 = slice 0
#define TOTAL_F4  (SLICE0_F4 * BATCH)        // 22,906,304

// Per-cell linked lists. Sentinel = 0; entries store pid+1.
__device__ int d_head[NCELLS_PAD];           // 1.4 MB
__device__ int d_next[NPOINTS];              // 0.5 MB

// ---------------------------------------------------------------------------
// K0: reset list heads (int4 stores, one wave). Also leaves the head array
// L2-resident for K1's exchanges and K2's reads. Off the critical path
// (hidden under K2's pre-sync store stream via the PDL chain).
// ---------------------------------------------------------------------------
__global__ void __launch_bounds__(256)
init_heads_kernel() {
    int i = blockIdx.x * blockDim.x + threadIdx.x;
    int4* h4 = (int4*)d_head;
    const int n4 = NCELLS_PAD / 4;           // 89,478
    const int stride = gridDim.x * blockDim.x;
    for (; i < n4; i += stride) {
        h4[i] = make_int4(0, 0, 0, 0);
    }
}

// ---------------------------------------------------------------------------
// K1 (PDL over K0): build per-cell lists. cell = round-half-to-even(c+35)
// per axis (faithful to jnp.round); out-of-box points excluded (they add
// exactly +0.0 in the reference). ALL B*N points map into batch slice 0
// (reference's tf.zeros batch column). Stores pid+1 (0 = end of list).
// ---------------------------------------------------------------------------
__global__ void __launch_bounds__(256)
build_lists_kernel(const float* __restrict__ coords) {
    int i = blockIdx.x * blockDim.x + threadIdx.x;    // 0 .. NPOINTS-1
    float c0 = __ldg(&coords[i * 3 + 0]);
    float c1 = __ldg(&coords[i * 3 + 1]);
    float c2 = __ldg(&coords[i * 3 + 2]);
    int g0 = __float2int_rn(c0 + MAX_DIST);
    int g1 = __float2int_rn(c1 + MAX_DIST);
    int g2 = __float2int_rn(c2 + MAX_DIST);

    cudaGridDependencySynchronize();   // K0's head init must be visible
    if ((unsigned)g0 < BOX && (unsigned)g1 < BOX && (unsigned)g2 < BOX) {
        int cell = (g0 * BOX + g1) * BOX + g2;
        d_next[i] = atomicExch(&d_head[cell], i + 1);
    }
}

// ---------------------------------------------------------------------------
// K2 (PDL over K1): gather + zero. One thread per (cell, quad).
//   1. 6 zero batches into slices 1..6 (pre-sync; overlaps K0+K1),
//   2. PDL sync, ISSUE the head load immediately,
//   3. 1 zero batch into slice 7 (hides the head-load latency without
//      flooding the LSU during the walk — R13's 3 post batches regressed),
//   4. walk the cell's list accumulating feats[pid*8+q] (8 quad-threads of
//      a cell share one warp -> 128B-coalesced feature reads; head/next
//      are L2-resident),
//   5. stream the accumulated float4 as the slice-0 value.
// Every output byte written exactly once; no atomics on the output.
// ---------------------------------------------------------------------------
__global__ void __launch_bounds__(256)
gather_zero_kernel(const float4* __restrict__ feats,
                   float* __restrict__ out) {
    const int tid = blockIdx.x * blockDim.x + threadIdx.x;
    if (tid >= SLICE0_F4) return;                  // 72 pad threads

    float4* out4 = (float4*)out;
    const float4 z = make_float4(0.f, 0.f, 0.f, 0.f);

    // Pre-sync zeros: slices 1..6 (274 MB grid-wide, covers K0+K1 runtime).
    #pragma unroll
    for (int k = 1; k <= 6; k++) {
        __stcs(&out4[(long long)k * SLICE0_F4 + tid], z);
    }

    cudaGridDependencySynchronize();               // wait for K1's lists

    const int cell = tid >> 3;
    const int q = tid & 7;

    int e = d_head[cell];                          // issue load NOW (L2 hit)

    // One post-sync batch hides the head-load latency.
    __stcs(&out4[(long long)7 * SLICE0_F4 + tid], z);

    float4 acc = z;
    while (e != 0) {
        int pid = e - 1;
        float4 v = __ldg(&feats[(long long)pid * 8 + q]);
        acc.x += v.x; acc.y += v.y; acc.z += v.z; acc.w += v.w;
        e = d_next[pid];
    }
    __stcs(&out4[tid], acc);                       // slice 0, written once
}

extern "C" void kernel_launch(void* const* d_in, const int* in_sizes, int n_in,
                              void* d_out, int out_size) {
    const float* coords = (const float*)d_in[0];     // [8,16384,3] f32
    const float4* feats = (const float4*)d_in[1];    // [8,16384,32] f32 as float4
    float* out = (float*)d_out;                      // [8,71,71,71,32] f32

    cudaLaunchAttribute pdl[1];
    pdl[0].id = cudaLaunchAttributeProgrammaticStreamSerialization;
    pdl[0].val.programmaticStreamSerializationAllowed = 1;

    // K0: reset + warm heads (one wave, int4).
    init_heads_kernel<<<350, 256>>>();

    // K1: build lists — PDL early launch over K0.
    {
        cudaLaunchConfig_t cfg = {};
        cfg.gridDim = dim3(NPOINTS / 256, 1, 1);     // 512 blocks
        cfg.blockDim = dim3(256, 1, 1);
        cfg.attrs = pdl; cfg.numAttrs = 1;
        cudaLaunchKernelEx(&cfg, build_lists_kernel, coords);
    }

    // K2: gather + zero — PDL early launch over K1.
    {
        cudaLaunchConfig_t cfg = {};
        cfg.gridDim = dim3((SLICE0_F4 + 255) / 256, 1, 1);  // 11185 blocks
        cfg.blockDim = dim3(256, 1, 1);
        cfg.attrs = pdl; cfg.numAttrs = 1;
        cudaLaunchKernelEx(&cfg, gather_zero_kernel, feats, out);
    }
}